// round 5
// baseline (speedup 1.0000x reference)
#include <cuda_runtime.h>
#include <cuda_bf16.h>

// BentPrototypeQuantizer: codebook == all 64 vertices of {-1,+1}^6 (proved R0,
// rel_err=0.0 every round). Nearest vertex separable: q_d = (x_d>0)?+1:-1
// (compare form keeps x==+0.0 -> -1 tie identical to reference).
// Pure stream: 25.2 MB in + 25.2 MB out; profiled floor ~5.1 TB/s R+W.
//
// R5: 256-bit vector memory ops (sm_100 ld/st.global.v8.f32) to halve the
// LDG/STG instruction count per byte. 2x 32B loads per thread front-batched,
// 256 threads, 1536 CTAs (one full wave at occ 8) — byte-geometry of the R2
// best (9.088us e2e), transaction width doubled.

#define THREADS 256
#define ITEMS 2                      // v8 (32B) chunks per thread
#define FLOATS_PER_BLOCK (THREADS * ITEMS * 8)   // 4096

__global__ void __launch_bounds__(THREADS, 8)
bent_quantize_v8(const float* __restrict__ x, float* __restrict__ out) {
    size_t base = (size_t)blockIdx.x * FLOATS_PER_BLOCK + (size_t)threadIdx.x * 8;

    float a[ITEMS][8];
    #pragma unroll
    for (int k = 0; k < ITEMS; k++) {
        const float* p = x + base + (size_t)k * (THREADS * 8);
        asm volatile(
            "ld.global.nc.v8.f32 {%0,%1,%2,%3,%4,%5,%6,%7}, [%8];"
            : "=f"(a[k][0]), "=f"(a[k][1]), "=f"(a[k][2]), "=f"(a[k][3]),
              "=f"(a[k][4]), "=f"(a[k][5]), "=f"(a[k][6]), "=f"(a[k][7])
            : "l"(p));
    }

    #pragma unroll
    for (int k = 0; k < ITEMS; k++) {
        float q[8];
        #pragma unroll
        for (int j = 0; j < 8; j++)
            q[j] = (a[k][j] > 0.0f) ? 1.0f : -1.0f;
        float* p = out + base + (size_t)k * (THREADS * 8);
        asm volatile(
            "st.global.v8.f32 [%0], {%1,%2,%3,%4,%5,%6,%7,%8};"
            :: "l"(p),
               "f"(q[0]), "f"(q[1]), "f"(q[2]), "f"(q[3]),
               "f"(q[4]), "f"(q[5]), "f"(q[6]), "f"(q[7])
            : "memory");
    }
}

// Generic fallback: any element count.
__global__ void __launch_bounds__(THREADS)
bent_quantize_generic(const float* __restrict__ x, float* __restrict__ out, int n) {
    int i = blockIdx.x * blockDim.x + threadIdx.x;
    int stride = gridDim.x * blockDim.x;
    for (; i < n; i += stride) {
        float v = x[i];
        out[i] = (v > 0.0f) ? 1.0f : -1.0f;
    }
}

extern "C" void kernel_launch(void* const* d_in, const int* in_sizes, int n_in,
                              void* d_out, int out_size) {
    const float* x = (const float*)d_in[0];
    float* out = (float*)d_out;
    int n = in_sizes[0];

    if ((n % FLOATS_PER_BLOCK) == 0) {
        int blocks = n / FLOATS_PER_BLOCK;   // 1536 for the bench shape
        bent_quantize_v8<<<blocks, THREADS>>>(x, out);
    } else {
        int blocks = (n + THREADS - 1) / THREADS;
        if (blocks > 8192) blocks = 8192;
        if (blocks < 1) blocks = 1;
        bent_quantize_generic<<<blocks, THREADS>>>(x, out, n);
    }
}

// round 6
// speedup vs baseline: 1.1053x; 1.1053x over previous
#include <cuda_runtime.h>
#include <cuda_bf16.h>

// BentPrototypeQuantizer — converged form.
//
// Math (proved R0, rel_err=0.0 all rounds): the reference codebook is ALL 64
// vertices of {-1,+1}^6 (each bent function + complement => supports union to
// the full cube; k=64 == unique count). Nearest-vertex is separable:
// q_d = (x_d > 0) ? +1 : -1, compare form preserving the x==+0.0 -> -1 tie.
//
// Perf (R1-R5 evidence): profiled duration invariant at 9.54-9.92us across
// ITEMS {1,4,8}, float4/v8, 768-6144 CTAs => kernel sits at the achieved
// mixed-R/W DRAM roofline (~5.2 TB/s combined; 25.2MB in + 25.2MB out).
// Single wave / MLP / issue-rate all verified non-binding. This round locks
// the two best-profiling traits: one 256-bit ld/st per thread (v8, fewest
// instructions per byte) + maximum CTA count (3072) for finest scheduling
// granularity.

#define THREADS 256
#define FLOATS_PER_BLOCK (THREADS * 8)   // 2048 floats = 8KB per CTA

__global__ void __launch_bounds__(THREADS, 8)
bent_quantize_v8(const float* __restrict__ x, float* __restrict__ out) {
    size_t base = (size_t)blockIdx.x * FLOATS_PER_BLOCK + (size_t)threadIdx.x * 8;

    float a[8];
    const float* p = x + base;
    asm volatile(
        "ld.global.nc.v8.f32 {%0,%1,%2,%3,%4,%5,%6,%7}, [%8];"
        : "=f"(a[0]), "=f"(a[1]), "=f"(a[2]), "=f"(a[3]),
          "=f"(a[4]), "=f"(a[5]), "=f"(a[6]), "=f"(a[7])
        : "l"(p));

    float q[8];
    #pragma unroll
    for (int j = 0; j < 8; j++)
        q[j] = (a[j] > 0.0f) ? 1.0f : -1.0f;

    float* po = out + base;
    asm volatile(
        "st.global.v8.f32 [%0], {%1,%2,%3,%4,%5,%6,%7,%8};"
        :: "l"(po),
           "f"(q[0]), "f"(q[1]), "f"(q[2]), "f"(q[3]),
           "f"(q[4]), "f"(q[5]), "f"(q[6]), "f"(q[7])
        : "memory");
}

// Generic fallback: any element count.
__global__ void __launch_bounds__(THREADS)
bent_quantize_generic(const float* __restrict__ x, float* __restrict__ out, int n) {
    int i = blockIdx.x * blockDim.x + threadIdx.x;
    int stride = gridDim.x * blockDim.x;
    for (; i < n; i += stride) {
        float v = x[i];
        out[i] = (v > 0.0f) ? 1.0f : -1.0f;
    }
}

extern "C" void kernel_launch(void* const* d_in, const int* in_sizes, int n_in,
                              void* d_out, int out_size) {
    const float* x = (const float*)d_in[0];
    float* out = (float*)d_out;
    int n = in_sizes[0];

    if ((n % FLOATS_PER_BLOCK) == 0) {
        int blocks = n / FLOATS_PER_BLOCK;   // 3072 for the bench shape
        bent_quantize_v8<<<blocks, THREADS>>>(x, out);
    } else {
        int blocks = (n + THREADS - 1) / THREADS;
        if (blocks > 8192) blocks = 8192;
        if (blocks < 1) blocks = 1;
        bent_quantize_generic<<<blocks, THREADS>>>(x, out, n);
    }
}